// round 16
// baseline (speedup 1.0000x reference)
#include <cuda_runtime.h>
#include <cuda_fp16.h>
#include <math.h>
#include <stdint.h>

#define BB 2
#define NN 512
#define DD 256
#define HH 256
#define HH2 128
#define NTHREADS 256

// SMEM byte offsets (main kernel)
#define OFF_RED   64
#define OFF_BW    256      // float2[128]: {b2[c], W3[c]}
#define OFF_LF    1280     // float[512]: left rows i0,i1
#define OFF_EW    3328     // float[1024]: edge weights / probs (2 rows)
#define OFF_ZP    9472     // float[64][4]: partial z per (stacked row, N-warp)
#define OFF_B     12288    // 64KB: W2 fp16 [k=256][64 words] swizzled
#define OFF_A     77824    // 32KB: A tile fp16 (reused as agg scratch at end)
#define SMEM_TOTAL 110592

// Scratch (__device__ globals: allocation-free rule)
__device__ float    g_left[BB * NN * HH];
__device__ __half   g_right_h[BB * NN * HH];
__device__ __half   g_x_h[BB * NN * DD];
__device__ float    g_agg[BB * NN * DD];
__device__ uint32_t gB_img[16384];   // 64KB swizzled W2 fp16 image

// ---------------------------------------------------------------------------
// helpers
// ---------------------------------------------------------------------------
__device__ __forceinline__ uint32_t smem_u32(const void* p) {
    uint32_t a;
    asm("{ .reg .u64 t; cvta.to.shared.u64 t, %1; cvt.u32.u64 %0, t; }"
        : "=r"(a) : "l"(p));
    return a;
}
__device__ __forceinline__ uint32_t pack_f16x2(float lo, float hi) {
    uint32_t r;
    asm("cvt.rn.f16x2.f32 %0, %1, %2;" : "=r"(r) : "f"(hi), "f"(lo));
    return r;
}
__device__ __forceinline__ void ldsm_x4(uint32_t* r, uint32_t addr) {
    asm volatile("ldmatrix.sync.aligned.m8n8.x4.shared.b16 {%0,%1,%2,%3}, [%4];"
                 : "=r"(r[0]), "=r"(r[1]), "=r"(r[2]), "=r"(r[3]) : "r"(addr));
}
__device__ __forceinline__ void ldsm_x4_t(uint32_t* r, uint32_t addr) {
    asm volatile("ldmatrix.sync.aligned.m8n8.x4.trans.shared.b16 {%0,%1,%2,%3}, [%4];"
                 : "=r"(r[0]), "=r"(r[1]), "=r"(r[2]), "=r"(r[3]) : "r"(addr));
}
__device__ __forceinline__ void mma16816(float* d, const uint32_t* a,
                                         const uint32_t* b) {
    asm volatile(
        "mma.sync.aligned.m16n8k16.row.col.f32.f16.f16.f32 "
        "{%0,%1,%2,%3}, {%4,%5,%6,%7}, {%8,%9}, {%0,%1,%2,%3};"
        : "+f"(d[0]), "+f"(d[1]), "+f"(d[2]), "+f"(d[3])
        : "r"(a[0]), "r"(a[1]), "r"(a[2]), "r"(a[3]), "r"(b[0]), "r"(b[1]));
}

// ---------------------------------------------------------------------------
// Kernel A: left/right projections (right + x fp16), grid 256, block 1024.
// Thread = (h-col 0..255, dh 0..3). dh splits the d-range into 64-d quarters;
// each thread accumulates ALL 4 rows over its quarter; partials combined via
// smem. W1 warp-LDG count per CTA halved vs R13. CTAs 0-15 also build gB_img.
// ---------------------------------------------------------------------------
#define LR_ROWS 4
__global__ __launch_bounds__(1024) void lr_kernel(
    const float* __restrict__ x, const float* __restrict__ W1,
    const float* __restrict__ b1, const float* __restrict__ W2)
{
    const int tid = threadIdx.x;
    const int bx = blockIdx.x;

    // merged bprep (first 16 CTAs x 1024 threads = 16384 words exactly)
    if (bx < 16) {
        int idx = bx * 1024 + tid;
        int k = idx >> 6;
        int w = idx & 63;
        float2 v = ((const float2*)W2)[k * 64 + w];
        uint32_t packed = pack_f16x2(v.x, v.y);
        uint32_t off = (uint32_t)(k * 256 + ((((w >> 2) ^ (k & 7)) << 4)) +
                                  (w & 3) * 4);
        gB_img[off >> 2] = packed;
    }

    __shared__ float sx[LR_ROWS][DD];              // 4KB
    __shared__ float sP[4 * LR_ROWS * 2 * HH];     // 32KB: [dh][row][l/r][h]
    const int r0 = bx * LR_ROWS;
    const int h = tid & 255;
    const int dh = tid >> 8;                       // 0..3 -> 64-d quarter
    const int d0 = dh << 6;

    // stage x + write g_x_h (coalesced; 1024 elems, one per thread)
    {
        int t = tid >> 8;
        int d = tid & 255;
        float xv = x[(r0 + t) * DD + d];
        sx[t][d] = xv;
        g_x_h[(r0 + t) * DD + d] = __float2half(xv);
    }
    __syncthreads();

    float l[LR_ROWS], r[LR_ROWS];
    const float b1v = (dh == 0) ? b1[h] : 0.f;
#pragma unroll
    for (int t = 0; t < LR_ROWS; t++) { l[t] = b1v; r[t] = 0.f; }

    // double-buffered W1 quads over this thread's 64-d quarter
    float wl[2][4], wr[2][4];
#pragma unroll
    for (int q = 0; q < 4; q++) {
        wl[0][q] = W1[(d0 + q) * HH + h];
        wr[0][q] = W1[(DD + d0 + q) * HH + h];
    }
#pragma unroll 2
    for (int dd = 0; dd < 64; dd += 4) {
        const int cur = (dd >> 2) & 1;
        const int d = d0 + dd;
        if (dd + 4 < 64) {
#pragma unroll
            for (int q = 0; q < 4; q++) {
                wl[cur ^ 1][q] = W1[(d + 4 + q) * HH + h];
                wr[cur ^ 1][q] = W1[(DD + d + 4 + q) * HH + h];
            }
        }
#pragma unroll
        for (int t = 0; t < LR_ROWS; t++) {
            float4 xv = *(const float4*)&sx[t][d];
            l[t] = fmaf(xv.x, wl[cur][0], l[t]); r[t] = fmaf(xv.x, wr[cur][0], r[t]);
            l[t] = fmaf(xv.y, wl[cur][1], l[t]); r[t] = fmaf(xv.y, wr[cur][1], r[t]);
            l[t] = fmaf(xv.z, wl[cur][2], l[t]); r[t] = fmaf(xv.z, wr[cur][2], r[t]);
            l[t] = fmaf(xv.w, wl[cur][3], l[t]); r[t] = fmaf(xv.w, wr[cur][3], r[t]);
        }
    }
    // write partials: sP[dh][row][stream][h]
#pragma unroll
    for (int t = 0; t < LR_ROWS; t++) {
        sP[dh * 2048 + t * 512 + 0 * 256 + h] = l[t];
        sP[dh * 2048 + t * 512 + 1 * 256 + h] = r[t];
    }
    __syncthreads();

    // combine quarters: 2048 outputs over 1024 threads (2 each)
#pragma unroll
    for (int k = tid; k < 2048; k += 1024) {
        float v = (sP[k] + sP[k + 2048]) + (sP[k + 4096] + sP[k + 6144]);
        int row = r0 + (k >> 9);
        int rem = k & 511;
        int hh2 = rem & 255;
        if (rem < 256) g_left[row * HH + hh2] = v;
        else           g_right_h[row * HH + hh2] = __float2half(v);
    }
}

// ---------------------------------------------------------------------------
// Kernel B: per (b, i-pair) — fp16 mma pair-MLP, j-tile 32, 2 CTAs/SM,
// register-prefetched right tiles. Writes agg rows to g_agg.
// (Byte-identical to the validated 163.9us kernel.)
// ---------------------------------------------------------------------------
__global__ __launch_bounds__(NTHREADS, 2)
void main_kernel(
    const float* __restrict__ base_adj,
    const float* __restrict__ b2, const float* __restrict__ W3,
    const float* __restrict__ b3)
{
    extern __shared__ char smem[];
    const uint32_t sbase = smem_u32(smem);
    const int i0 = blockIdx.x * 2;
    const int b = blockIdx.y;
    const int tid = threadIdx.x;
    const int wid = tid >> 5;
    const int lid = tid & 31;

    float*  sRed = (float*)(smem + OFF_RED);
    float2* sBW  = (float2*)(smem + OFF_BW);
    float*  sLf  = (float*)(smem + OFF_LF);
    float*  sEw  = (float*)(smem + OFF_EW);
    float*  sZp  = (float*)(smem + OFF_ZP);

    // Stage B tile (pre-swizzled) + left rows + b2/W3 pairs
    {
        const uint4* src = (const uint4*)gB_img;
        uint4* dst = (uint4*)(smem + OFF_B);
#pragma unroll
        for (int t = tid; t < 4096; t += NTHREADS) dst[t] = src[t];
    }
    sLf[tid]       = g_left[((size_t)(b * NN + i0)) * HH + tid];
    sLf[256 + tid] = g_left[((size_t)(b * NN + i0 + 1)) * HH + tid];
    if (tid < HH2) sBW[tid] = make_float2(b2[tid], W3[tid]);

    const float bias3 = b3[0];

    // A-build constants: thread covers k quad kq, j stride 4
    const int jp = tid >> 6;               // 0..3
    const int kq = tid & 63;               // 0..63
    __syncthreads();
    const float4 lfv0 = *(const float4*)&sLf[kq * 4];
    const float4 lfv1 = *(const float4*)&sLf[256 + kq * 4];
    const uint32_t a_word_xorbase = (uint32_t)(kq >> 1) << 4;
    const uint32_t a_word_lo = (uint32_t)(kq & 1) << 3;

    // MMA addressing: warp = (wy 0..1 stacked-M half of 32, wx 0..3 N-slot of 32)
    const int wy = wid & 1;
    const int wx = wid >> 1;
    const int gid = lid >> 2, tig = lid & 3;
    const uint32_t hi16 = (uint32_t)lid >> 4;
    const int rowA0 = wy * 32 + (lid & 15);
    const uint32_t aRow0 = sbase + OFF_A + rowA0 * 512;
    const uint32_t a_xor = (uint32_t)(rowA0 & 7) << 4;
    const int b_k = lid & 15;
    const uint32_t b_row0 = sbase + OFF_B + b_k * 256;
    const uint32_t b_xor = (uint32_t)(b_k & 7) << 4;
    const uint32_t bsel0 = ((uint32_t)((wx * 2) * 2 + (int)hi16) << 4) ^ b_xor;
    const uint32_t bsel1 = ((uint32_t)((wx * 2 + 1) * 2 + (int)hi16) << 4) ^ b_xor;

    const __half* rbB = g_right_h + ((size_t)(b * NN)) * HH;

    // prefetch tile 0
    uint2 pf[8];
#pragma unroll
    for (int it = 0; it < 8; it++) {
        int j = it * 4 + jp;
        pf[it] = *(const uint2*)&rbB[j * HH + kq * 4];
    }

    // ---- 16 j-tiles of 32 ----
    for (int jt = 0; jt < 16; jt++) {
        const int j0 = jt * 32;

        // Combine previous tile's z partials
        if (jt && tid < 64) {
            float z = sZp[tid * 4] + sZp[tid * 4 + 1] + sZp[tid * 4 + 2] +
                      sZp[tid * 4 + 3] + bias3;
            int isel = tid >> 5;
            sEw[isel * 512 + j0 - 32 + (tid & 31)] = 1.f / (1.f + expf(-z));
        }

        // Build stacked A tile from prefetched regs: rows 0..31=i0, 32..63=i1
        uint2 cv[8];
#pragma unroll
        for (int it = 0; it < 8; it++) cv[it] = pf[it];

#pragma unroll
        for (int it = 0; it < 8; it++) {
            int j = it * 4 + jp;
            float2 f0 = __half22float2(*(__half2*)&cv[it].x);
            float2 f1 = __half22float2(*(__half2*)&cv[it].y);
            uint32_t w0 = pack_f16x2(fmaxf(lfv0.x + f0.x, 0.f), fmaxf(lfv0.y + f0.y, 0.f));
            uint32_t w1 = pack_f16x2(fmaxf(lfv0.z + f1.x, 0.f), fmaxf(lfv0.w + f1.y, 0.f));
            uint32_t off = (uint32_t)(j * 512) +
                           (a_word_xorbase ^ ((uint32_t)(j & 7) << 4)) + a_word_lo;
            asm volatile("st.shared.v2.b32 [%0], {%1, %2};"
                         :: "r"(sbase + OFF_A + off), "r"(w0), "r"(w1) : "memory");
            int j2 = j + 32;
            uint32_t w2 = pack_f16x2(fmaxf(lfv1.x + f0.x, 0.f), fmaxf(lfv1.y + f0.y, 0.f));
            uint32_t w3p = pack_f16x2(fmaxf(lfv1.z + f1.x, 0.f), fmaxf(lfv1.w + f1.y, 0.f));
            uint32_t off2 = (uint32_t)(j2 * 512) +
                            (a_word_xorbase ^ ((uint32_t)(j2 & 7) << 4)) + a_word_lo;
            asm volatile("st.shared.v2.b32 [%0], {%1, %2};"
                         :: "r"(sbase + OFF_A + off2), "r"(w2), "r"(w3p) : "memory");
        }

        // Prefetch next tile BEFORE the sync (independent of A stores)
        if (jt < 15) {
            const __half* rbn = rbB + ((size_t)(j0 + 32)) * HH;
#pragma unroll
            for (int it = 0; it < 8; it++) {
                int j = it * 4 + jp;
                pf[it] = *(const uint2*)&rbn[j * HH + kq * 4];
            }
        }
        __syncthreads();

        // ---- warp GEMM: D[32,32] = A(rows wy*32..+31)[32,256] @ B[256,32] ----
        float acc[2][4][4];
#pragma unroll
        for (int mt = 0; mt < 2; mt++)
#pragma unroll
            for (int g = 0; g < 4; g++)
#pragma unroll
                for (int c = 0; c < 4; c++) acc[mt][g][c] = 0.f;

#pragma unroll 4
        for (int s = 0; s < 16; s++) {
            uint32_t a0[4], a1[4], bb0[4], bb1[4];
            uint32_t chunk = ((uint32_t)(2 * s + (int)hi16) << 4) ^ a_xor;
            ldsm_x4(a0, aRow0 + chunk);
            ldsm_x4(a1, aRow0 + 16 * 512 + chunk);
            uint32_t brow = b_row0 + (uint32_t)s * 4096;
            ldsm_x4_t(bb0, brow + bsel0);
            ldsm_x4_t(bb1, brow + bsel1);
            mma16816(acc[0][0], a0, &bb0[0]);
            mma16816(acc[0][1], a0, &bb0[2]);
            mma16816(acc[0][2], a0, &bb1[0]);
            mma16816(acc[0][3], a0, &bb1[2]);
            mma16816(acc[1][0], a1, &bb0[0]);
            mma16816(acc[1][1], a1, &bb0[2]);
            mma16816(acc[1][2], a1, &bb1[0]);
            mma16816(acc[1][3], a1, &bb1[2]);
        }

        // ---- epilogue: partial z over this warp's 32 cols ----
#pragma unroll
        for (int mt = 0; mt < 2; mt++) {
            float z0 = 0.f, z1 = 0.f;
#pragma unroll
            for (int g = 0; g < 4; g++) {
                int c0 = wx * 32 + g * 8 + tig * 2;
                float2 bw0 = sBW[c0];
                float2 bw1 = sBW[c0 + 1];
                z0 = fmaf(fmaxf(acc[mt][g][0] + bw0.x, 0.f), bw0.y, z0);
                z0 = fmaf(fmaxf(acc[mt][g][1] + bw1.x, 0.f), bw1.y, z0);
                z1 = fmaf(fmaxf(acc[mt][g][2] + bw0.x, 0.f), bw0.y, z1);
                z1 = fmaf(fmaxf(acc[mt][g][3] + bw1.x, 0.f), bw1.y, z1);
            }
            z0 += __shfl_xor_sync(0xffffffffu, z0, 1);
            z0 += __shfl_xor_sync(0xffffffffu, z0, 2);
            z1 += __shfl_xor_sync(0xffffffffu, z1, 1);
            z1 += __shfl_xor_sync(0xffffffffu, z1, 2);
            if (tig == 0) {
                int rr = wy * 32 + mt * 16 + gid;      // 0..63, each once
                sZp[rr * 4 + wx]       = z0;
                sZp[(rr + 8) * 4 + wx] = z1;
            }
        }
        __syncthreads();
    }
    // combine last tile
    if (tid < 64) {
        float z = sZp[tid * 4] + sZp[tid * 4 + 1] + sZp[tid * 4 + 2] +
                  sZp[tid * 4 + 3] + bias3;
        int isel = tid >> 5;
        sEw[isel * 512 + 480 + (tid & 31)] = 1.f / (1.f + expf(-z));
    }
    __syncthreads();

    // ---- softmax per query row g ----
#pragma unroll
    for (int g = 0; g < 2; g++) {
        const int ii = i0 + g;
        const float* ba = base_adj + ((size_t)(b * NN + ii)) * NN;
        float* ew = sEw + g * 512;
        int ja = tid, jb = tid + 256;
        float v0 = ba[ja] * ew[ja] + (ja == ii ? 1.f : 0.f);
        float v1 = ba[jb] * ew[jb] + (jb == ii ? 1.f : 0.f);

        float m = fmaxf(v0, v1);
#pragma unroll
        for (int off = 16; off > 0; off >>= 1)
            m = fmaxf(m, __shfl_xor_sync(0xffffffffu, m, off));
        if (lid == 0) sRed[wid] = m;
        __syncthreads();
        if (tid == 0) {
            float mm = sRed[0];
#pragma unroll
            for (int w = 1; w < 8; w++) mm = fmaxf(mm, sRed[w]);
            sRed[0] = mm;
        }
        __syncthreads();
        m = sRed[0];
        __syncthreads();

        float e0 = expf(v0 - m);
        float e1 = expf(v1 - m);
        float s = e0 + e1;
#pragma unroll
        for (int off = 16; off > 0; off >>= 1)
            s += __shfl_xor_sync(0xffffffffu, s, off);
        if (lid == 0) sRed[wid] = s;
        __syncthreads();
        if (tid == 0) {
            float ss = 0.f;
#pragma unroll
            for (int w = 0; w < 8; w++) ss += sRed[w];
            sRed[0] = ss;
        }
        __syncthreads();
        const float inv = 1.f / sRed[0];
        ew[ja] = e0 * inv;
        ew[jb] = e1 * inv;
        __syncthreads();
    }

    // ---- agg: vectorized __half2 x loads; halves combined via smem ----
    {
        // thread = (jh 0/1, d2 0..127); d = 2*d2
        const int d2 = tid & 127;
        const int jh = tid >> 7;
        const __half2* xb2 = (const __half2*)(g_x_h + (size_t)b * NN * DD);
        const float* p0 = sEw + jh * 256;          // row i0, this j-half
        const float* p1 = sEw + 512 + jh * 256;    // row i1, this j-half
        const int jbase = jh * 256;

        float2 a0 = make_float2(0.f, 0.f);
        float2 a1 = make_float2(0.f, 0.f);
#pragma unroll 4
        for (int j = 0; j < 256; j++) {
            float2 xv = __half22float2(xb2[(size_t)(jbase + j) * 128 + d2]);
            float w0 = p0[j], w1 = p1[j];
            a0.x = fmaf(w0, xv.x, a0.x);
            a0.y = fmaf(w0, xv.y, a0.y);
            a1.x = fmaf(w1, xv.x, a1.x);
            a1.y = fmaf(w1, xv.y, a1.y);
        }
        // scratch in the (now free) A-tile region: [jh][row][256 floats]
        float* sc = (float*)(smem + OFF_A);
        *(float2*)&sc[(jh * 2 + 0) * 256 + d2 * 2] = a0;
        *(float2*)&sc[(jh * 2 + 1) * 256 + d2 * 2] = a1;
        __syncthreads();
        // combine halves: 512 outputs over 256 threads
        float v0 = sc[0 * 256 + tid] + sc[2 * 256 + tid];   // row i0
        float v1 = sc[1 * 256 + tid] + sc[3 * 256 + tid];   // row i1
        g_agg[((size_t)(b * NN + i0)) * DD + tid]     = v0;
        g_agg[((size_t)(b * NN + i0 + 1)) * DD + tid] = v1;
    }
}

// ---------------------------------------------------------------------------
// Kernel C: out = g_agg @ Wg + bg; grid 128, block 1024.
// Thread = (h-col, dh 0..3); dh splits d into 64-d quarters, 8 rows/thread;
// smem combine.
// ---------------------------------------------------------------------------
__global__ __launch_bounds__(1024) void out_kernel(
    const float* __restrict__ Wg, const float* __restrict__ bg,
    float* __restrict__ out)
{
    __shared__ float sA[8 * DD];            // 8KB
    __shared__ float sP[4 * 8 * HH];        // 32KB: [dh][row][h]
    const int r0 = blockIdx.x * 8;
    const int tid = threadIdx.x;
    const int h = tid & 255;
    const int dh = tid >> 8;                // 0..3
    const int d0 = dh << 6;
    if (tid < 512) {
        const float4* src = (const float4*)(g_agg + (size_t)r0 * DD);
        float4* dst = (float4*)sA;
        dst[tid] = src[tid];
    }
    __syncthreads();

    float acc[8];
    const float bgv = (dh == 0) ? bg[h] : 0.f;
#pragma unroll
    for (int t = 0; t < 8; t++) acc[t] = bgv;

    float wq[2][4];
#pragma unroll
    for (int q = 0; q < 4; q++) wq[0][q] = Wg[(d0 + q) * HH + h];
#pragma unroll 2
    for (int dd = 0; dd < 64; dd += 4) {
        const int cur = (dd >> 2) & 1;
        const int d = d0 + dd;
        if (dd + 4 < 64) {
#pragma unroll
            for (int q = 0; q < 4; q++)
                wq[cur ^ 1][q] = Wg[(d + 4 + q) * HH + h];
        }
#pragma unroll
        for (int t = 0; t < 8; t++) {
            float4 av = *(const float4*)&sA[t * DD + d];
            acc[t] = fmaf(av.x, wq[cur][0],
                     fmaf(av.y, wq[cur][1],
                     fmaf(av.z, wq[cur][2],
                     fmaf(av.w, wq[cur][3], acc[t]))));
        }
    }
#pragma unroll
    for (int t = 0; t < 8; t++)
        sP[dh * 2048 + t * 256 + h] = acc[t];
    __syncthreads();

#pragma unroll
    for (int k = tid; k < 2048; k += 1024) {
        float v = (sP[k] + sP[k + 2048]) + (sP[k + 4096] + sP[k + 6144]);
        int row = r0 + (k >> 8);
        out[(size_t)row * HH + (k & 255)] = v;
    }
}

// ---------------------------------------------------------------------------
extern "C" void kernel_launch(void* const* d_in, const int* in_sizes, int n_in,
                              void* d_out, int out_size)
{
    const float* x        = (const float*)d_in[0];
    const float* base_adj = (const float*)d_in[1];
    const float* W1       = (const float*)d_in[2];
    const float* b1       = (const float*)d_in[3];
    const float* W2       = (const float*)d_in[4];
    const float* b2       = (const float*)d_in[5];
    const float* W3       = (const float*)d_in[6];
    const float* b3       = (const float*)d_in[7];
    const float* Wg       = (const float*)d_in[8];
    const float* bg       = (const float*)d_in[9];
    float* out = (float*)d_out;

    cudaFuncSetAttribute(main_kernel,
                         cudaFuncAttributeMaxDynamicSharedMemorySize,
                         SMEM_TOTAL);

    lr_kernel<<<BB * NN / LR_ROWS, 1024>>>(x, W1, b1, W2);
    main_kernel<<<dim3(NN / 2, BB), NTHREADS, SMEM_TOTAL>>>(
        base_adj, b2, W3, b3);
    out_kernel<<<BB * NN / 8, 1024>>>(Wg, bg, out);
}

// round 17
// speedup vs baseline: 1.0292x; 1.0292x over previous
#include <cuda_runtime.h>
#include <cuda_fp16.h>
#include <math.h>
#include <stdint.h>

#define BB 2
#define NN 512
#define DD 256
#define HH 256
#define HH2 128
#define NTHREADS 256

// SMEM byte offsets (main kernel)
#define OFF_RED   64
#define OFF_BW    256      // float2[128]: {b2[c], W3[c]}
#define OFF_LF    1280     // float[512]: left rows i0,i1
#define OFF_EW    3328     // float[1024]: edge weights / probs (2 rows)
#define OFF_ZP    9472     // float[64][4]: partial z per (stacked row, N-warp)
#define OFF_B     12288    // 64KB: W2 fp16 [k=256][64 words] swizzled
#define OFF_A     77824    // 32KB: A tile fp16 (reused as agg scratch at end)
#define SMEM_TOTAL 110592

// Scratch (__device__ globals: allocation-free rule)
__device__ float    g_left[BB * NN * HH];
__device__ __half   g_right_h[BB * NN * HH];
__device__ __half   g_x_h[BB * NN * DD];
__device__ float    g_agg[BB * NN * DD];
__device__ uint32_t gB_img[16384];   // 64KB swizzled W2 fp16 image

// ---------------------------------------------------------------------------
// helpers
// ---------------------------------------------------------------------------
__device__ __forceinline__ uint32_t smem_u32(const void* p) {
    uint32_t a;
    asm("{ .reg .u64 t; cvta.to.shared.u64 t, %1; cvt.u32.u64 %0, t; }"
        : "=r"(a) : "l"(p));
    return a;
}
__device__ __forceinline__ uint32_t pack_f16x2(float lo, float hi) {
    uint32_t r;
    asm("cvt.rn.f16x2.f32 %0, %1, %2;" : "=r"(r) : "f"(hi), "f"(lo));
    return r;
}
__device__ __forceinline__ void ldsm_x4(uint32_t* r, uint32_t addr) {
    asm volatile("ldmatrix.sync.aligned.m8n8.x4.shared.b16 {%0,%1,%2,%3}, [%4];"
                 : "=r"(r[0]), "=r"(r[1]), "=r"(r[2]), "=r"(r[3]) : "r"(addr));
}
__device__ __forceinline__ void ldsm_x4_t(uint32_t* r, uint32_t addr) {
    asm volatile("ldmatrix.sync.aligned.m8n8.x4.trans.shared.b16 {%0,%1,%2,%3}, [%4];"
                 : "=r"(r[0]), "=r"(r[1]), "=r"(r[2]), "=r"(r[3]) : "r"(addr));
}
__device__ __forceinline__ void mma16816(float* d, const uint32_t* a,
                                         const uint32_t* b) {
    asm volatile(
        "mma.sync.aligned.m16n8k16.row.col.f32.f16.f16.f32 "
        "{%0,%1,%2,%3}, {%4,%5,%6,%7}, {%8,%9}, {%0,%1,%2,%3};"
        : "+f"(d[0]), "+f"(d[1]), "+f"(d[2]), "+f"(d[3])
        : "r"(a[0]), "r"(a[1]), "r"(a[2]), "r"(a[3]), "r"(b[0]), "r"(b[1]));
}

// ---------------------------------------------------------------------------
// Kernel A: left/right projections (right + x fp16), grid 256, block 512.
// Thread = (h-col 0..255, dh 0..1): dh splits d-range; 4 rows per thread;
// partials combined via smem. (R14-validated configuration.)
// CTAs 0-31 also build the swizzled W2 image.
// ---------------------------------------------------------------------------
#define LR_ROWS 4
__global__ __launch_bounds__(512) void lr_kernel(
    const float* __restrict__ x, const float* __restrict__ W1,
    const float* __restrict__ b1, const float* __restrict__ W2)
{
    const int tid = threadIdx.x;
    const int bx = blockIdx.x;

    // merged bprep (first 32 CTAs x 512 threads = 16384 words exactly)
    if (bx < 32) {
        int idx = bx * 512 + tid;
        int k = idx >> 6;
        int w = idx & 63;
        float2 v = ((const float2*)W2)[k * 64 + w];
        uint32_t packed = pack_f16x2(v.x, v.y);
        uint32_t off = (uint32_t)(k * 256 + ((((w >> 2) ^ (k & 7)) << 4)) +
                                  (w & 3) * 4);
        gB_img[off >> 2] = packed;
    }

    __shared__ float sx[LR_ROWS][DD];          // 4KB
    __shared__ float sP[2 * LR_ROWS * 2 * HH]; // 16KB: [dh][row][l/r][h]
    const int r0 = bx * LR_ROWS;
    const int h = tid & 255;
    const int dh = tid >> 8;                   // 0/1 -> d range
    const int d0 = dh << 7;

    // stage x + write g_x_h (coalesced)
#pragma unroll
    for (int idx = tid; idx < LR_ROWS * DD; idx += 512) {
        int t = idx >> 8;
        int d = idx & 255;
        float xv = x[(r0 + t) * DD + d];
        sx[t][d] = xv;
        g_x_h[(r0 + t) * DD + d] = __float2half(xv);
    }
    __syncthreads();

    float l[LR_ROWS], r[LR_ROWS];
    const float b1v = (dh == 0) ? b1[h] : 0.f;
#pragma unroll
    for (int t = 0; t < LR_ROWS; t++) { l[t] = b1v; r[t] = 0.f; }

    // double-buffered W1 quads over this thread's 128-d half
    float wl[2][4], wr[2][4];
#pragma unroll
    for (int q = 0; q < 4; q++) {
        wl[0][q] = W1[(d0 + q) * HH + h];
        wr[0][q] = W1[(DD + d0 + q) * HH + h];
    }
#pragma unroll 2
    for (int dd = 0; dd < 128; dd += 4) {
        const int cur = (dd >> 2) & 1;
        const int d = d0 + dd;
        if (dd + 4 < 128) {
#pragma unroll
            for (int q = 0; q < 4; q++) {
                wl[cur ^ 1][q] = W1[(d + 4 + q) * HH + h];
                wr[cur ^ 1][q] = W1[(DD + d + 4 + q) * HH + h];
            }
        }
#pragma unroll
        for (int t = 0; t < LR_ROWS; t++) {
            float4 xv = *(const float4*)&sx[t][d];
            l[t] = fmaf(xv.x, wl[cur][0], l[t]); r[t] = fmaf(xv.x, wr[cur][0], r[t]);
            l[t] = fmaf(xv.y, wl[cur][1], l[t]); r[t] = fmaf(xv.y, wr[cur][1], r[t]);
            l[t] = fmaf(xv.z, wl[cur][2], l[t]); r[t] = fmaf(xv.z, wr[cur][2], r[t]);
            l[t] = fmaf(xv.w, wl[cur][3], l[t]); r[t] = fmaf(xv.w, wr[cur][3], r[t]);
        }
    }
    // write partials: sP[dh][row][stream][h]
#pragma unroll
    for (int t = 0; t < LR_ROWS; t++) {
        sP[dh * 2048 + t * 512 + 0 * 256 + h] = l[t];
        sP[dh * 2048 + t * 512 + 1 * 256 + h] = r[t];
    }
    __syncthreads();

    // combine halves: 2048 outputs over 512 threads
#pragma unroll
    for (int k = tid; k < 2048; k += 512) {
        float v = sP[k] + sP[k + 2048];
        int row = r0 + (k >> 9);
        int rem = k & 511;
        int hh2 = rem & 255;
        if (rem < 256) g_left[row * HH + hh2] = v;
        else           g_right_h[row * HH + hh2] = __float2half(v);
    }
}

// ---------------------------------------------------------------------------
// Kernel B: per (b, i-pair) — fp16 mma pair-MLP, j-tile 32, 2 CTAs/SM,
// register-prefetched right tiles, parallel 2-row softmax. Writes g_agg.
// ---------------------------------------------------------------------------
__global__ __launch_bounds__(NTHREADS, 2)
void main_kernel(
    const float* __restrict__ base_adj,
    const float* __restrict__ b2, const float* __restrict__ W3,
    const float* __restrict__ b3)
{
    extern __shared__ char smem[];
    const uint32_t sbase = smem_u32(smem);
    const int i0 = blockIdx.x * 2;
    const int b = blockIdx.y;
    const int tid = threadIdx.x;
    const int wid = tid >> 5;
    const int lid = tid & 31;

    float*  sRed = (float*)(smem + OFF_RED);
    float2* sBW  = (float2*)(smem + OFF_BW);
    float*  sLf  = (float*)(smem + OFF_LF);
    float*  sEw  = (float*)(smem + OFF_EW);
    float*  sZp  = (float*)(smem + OFF_ZP);

    // Stage B tile (pre-swizzled) + left rows + b2/W3 pairs
    {
        const uint4* src = (const uint4*)gB_img;
        uint4* dst = (uint4*)(smem + OFF_B);
#pragma unroll
        for (int t = tid; t < 4096; t += NTHREADS) dst[t] = src[t];
    }
    sLf[tid]       = g_left[((size_t)(b * NN + i0)) * HH + tid];
    sLf[256 + tid] = g_left[((size_t)(b * NN + i0 + 1)) * HH + tid];
    if (tid < HH2) sBW[tid] = make_float2(b2[tid], W3[tid]);

    const float bias3 = b3[0];

    // A-build constants: thread covers k quad kq, j stride 4
    const int jp = tid >> 6;               // 0..3
    const int kq = tid & 63;               // 0..63
    __syncthreads();
    const float4 lfv0 = *(const float4*)&sLf[kq * 4];
    const float4 lfv1 = *(const float4*)&sLf[256 + kq * 4];
    const uint32_t a_word_xorbase = (uint32_t)(kq >> 1) << 4;
    const uint32_t a_word_lo = (uint32_t)(kq & 1) << 3;

    // MMA addressing: warp = (wy 0..1 stacked-M half of 32, wx 0..3 N-slot of 32)
    const int wy = wid & 1;
    const int wx = wid >> 1;
    const int gid = lid >> 2, tig = lid & 3;
    const uint32_t hi16 = (uint32_t)lid >> 4;
    const int rowA0 = wy * 32 + (lid & 15);
    const uint32_t aRow0 = sbase + OFF_A + rowA0 * 512;
    const uint32_t a_xor = (uint32_t)(rowA0 & 7) << 4;
    const int b_k = lid & 15;
    const uint32_t b_row0 = sbase + OFF_B + b_k * 256;
    const uint32_t b_xor = (uint32_t)(b_k & 7) << 4;
    const uint32_t bsel0 = ((uint32_t)((wx * 2) * 2 + (int)hi16) << 4) ^ b_xor;
    const uint32_t bsel1 = ((uint32_t)((wx * 2 + 1) * 2 + (int)hi16) << 4) ^ b_xor;

    const __half* rbB = g_right_h + ((size_t)(b * NN)) * HH;

    // prefetch tile 0
    uint2 pf[8];
#pragma unroll
    for (int it = 0; it < 8; it++) {
        int j = it * 4 + jp;
        pf[it] = *(const uint2*)&rbB[j * HH + kq * 4];
    }

    // ---- 16 j-tiles of 32 ----
    for (int jt = 0; jt < 16; jt++) {
        const int j0 = jt * 32;

        // Combine previous tile's z partials
        if (jt && tid < 64) {
            float z = sZp[tid * 4] + sZp[tid * 4 + 1] + sZp[tid * 4 + 2] +
                      sZp[tid * 4 + 3] + bias3;
            int isel = tid >> 5;
            sEw[isel * 512 + j0 - 32 + (tid & 31)] = 1.f / (1.f + expf(-z));
        }

        // Build stacked A tile from prefetched regs: rows 0..31=i0, 32..63=i1
        uint2 cv[8];
#pragma unroll
        for (int it = 0; it < 8; it++) cv[it] = pf[it];

#pragma unroll
        for (int it = 0; it < 8; it++) {
            int j = it * 4 + jp;
            float2 f0 = __half22float2(*(__half2*)&cv[it].x);
            float2 f1 = __half22float2(*(__half2*)&cv[it].y);
            uint32_t w0 = pack_f16x2(fmaxf(lfv0.x + f0.x, 0.f), fmaxf(lfv0.y + f0.y, 0.f));
            uint32_t w1 = pack_f16x2(fmaxf(lfv0.z + f1.x, 0.f), fmaxf(lfv0.w + f1.y, 0.f));
            uint32_t off = (uint32_t)(j * 512) +
                           (a_word_xorbase ^ ((uint32_t)(j & 7) << 4)) + a_word_lo;
            asm volatile("st.shared.v2.b32 [%0], {%1, %2};"
                         :: "r"(sbase + OFF_A + off), "r"(w0), "r"(w1) : "memory");
            int j2 = j + 32;
            uint32_t w2 = pack_f16x2(fmaxf(lfv1.x + f0.x, 0.f), fmaxf(lfv1.y + f0.y, 0.f));
            uint32_t w3p = pack_f16x2(fmaxf(lfv1.z + f1.x, 0.f), fmaxf(lfv1.w + f1.y, 0.f));
            uint32_t off2 = (uint32_t)(j2 * 512) +
                            (a_word_xorbase ^ ((uint32_t)(j2 & 7) << 4)) + a_word_lo;
            asm volatile("st.shared.v2.b32 [%0], {%1, %2};"
                         :: "r"(sbase + OFF_A + off2), "r"(w2), "r"(w3p) : "memory");
        }

        // Prefetch next tile BEFORE the sync (independent of A stores)
        if (jt < 15) {
            const __half* rbn = rbB + ((size_t)(j0 + 32)) * HH;
#pragma unroll
            for (int it = 0; it < 8; it++) {
                int j = it * 4 + jp;
                pf[it] = *(const uint2*)&rbn[j * HH + kq * 4];
            }
        }
        __syncthreads();

        // ---- warp GEMM: D[32,32] = A(rows wy*32..+31)[32,256] @ B[256,32] ----
        float acc[2][4][4];
#pragma unroll
        for (int mt = 0; mt < 2; mt++)
#pragma unroll
            for (int g = 0; g < 4; g++)
#pragma unroll
                for (int c = 0; c < 4; c++) acc[mt][g][c] = 0.f;

#pragma unroll 4
        for (int s = 0; s < 16; s++) {
            uint32_t a0[4], a1[4], bb0[4], bb1[4];
            uint32_t chunk = ((uint32_t)(2 * s + (int)hi16) << 4) ^ a_xor;
            ldsm_x4(a0, aRow0 + chunk);
            ldsm_x4(a1, aRow0 + 16 * 512 + chunk);
            uint32_t brow = b_row0 + (uint32_t)s * 4096;
            ldsm_x4_t(bb0, brow + bsel0);
            ldsm_x4_t(bb1, brow + bsel1);
            mma16816(acc[0][0], a0, &bb0[0]);
            mma16816(acc[0][1], a0, &bb0[2]);
            mma16816(acc[0][2], a0, &bb1[0]);
            mma16816(acc[0][3], a0, &bb1[2]);
            mma16816(acc[1][0], a1, &bb0[0]);
            mma16816(acc[1][1], a1, &bb0[2]);
            mma16816(acc[1][2], a1, &bb1[0]);
            mma16816(acc[1][3], a1, &bb1[2]);
        }

        // ---- epilogue: partial z over this warp's 32 cols ----
#pragma unroll
        for (int mt = 0; mt < 2; mt++) {
            float z0 = 0.f, z1 = 0.f;
#pragma unroll
            for (int g = 0; g < 4; g++) {
                int c0 = wx * 32 + g * 8 + tig * 2;
                float2 bw0 = sBW[c0];
                float2 bw1 = sBW[c0 + 1];
                z0 = fmaf(fmaxf(acc[mt][g][0] + bw0.x, 0.f), bw0.y, z0);
                z0 = fmaf(fmaxf(acc[mt][g][1] + bw1.x, 0.f), bw1.y, z0);
                z1 = fmaf(fmaxf(acc[mt][g][2] + bw0.x, 0.f), bw0.y, z1);
                z1 = fmaf(fmaxf(acc[mt][g][3] + bw1.x, 0.f), bw1.y, z1);
            }
            z0 += __shfl_xor_sync(0xffffffffu, z0, 1);
            z0 += __shfl_xor_sync(0xffffffffu, z0, 2);
            z1 += __shfl_xor_sync(0xffffffffu, z1, 1);
            z1 += __shfl_xor_sync(0xffffffffu, z1, 2);
            if (tig == 0) {
                int rr = wy * 32 + mt * 16 + gid;      // 0..63, each once
                sZp[rr * 4 + wx]       = z0;
                sZp[(rr + 8) * 4 + wx] = z1;
            }
        }
        __syncthreads();
    }
    // combine last tile
    if (tid < 64) {
        float z = sZp[tid * 4] + sZp[tid * 4 + 1] + sZp[tid * 4 + 2] +
                  sZp[tid * 4 + 3] + bias3;
        int isel = tid >> 5;
        sEw[isel * 512 + 480 + (tid & 31)] = 1.f / (1.f + expf(-z));
    }
    __syncthreads();

    // ---- softmax: both rows in parallel (row = tid>>7, 4 j's/thread) ----
    {
        const int row = tid >> 7;              // 0/1
        const int t128 = tid & 127;
        const int ii = i0 + row;
        const float* ba = base_adj + ((size_t)(b * NN + ii)) * NN;
        float* ew = sEw + row * 512;
        const int jq = t128 * 4;

        float4 bav = *(const float4*)&ba[jq];
        float4 ewv = *(const float4*)&ew[jq];
        float v0 = bav.x * ewv.x + (jq     == ii ? 1.f : 0.f);
        float v1 = bav.y * ewv.y + (jq + 1 == ii ? 1.f : 0.f);
        float v2 = bav.z * ewv.z + (jq + 2 == ii ? 1.f : 0.f);
        float v3 = bav.w * ewv.w + (jq + 3 == ii ? 1.f : 0.f);

        float m = fmaxf(fmaxf(v0, v1), fmaxf(v2, v3));
#pragma unroll
        for (int off = 16; off > 0; off >>= 1)
            m = fmaxf(m, __shfl_xor_sync(0xffffffffu, m, off));
        if (lid == 0) sRed[wid] = m;           // wid 0..3 row0, 4..7 row1
        __syncthreads();
        m = fmaxf(fmaxf(sRed[row * 4], sRed[row * 4 + 1]),
                  fmaxf(sRed[row * 4 + 2], sRed[row * 4 + 3]));

        float e0 = expf(v0 - m);
        float e1 = expf(v1 - m);
        float e2 = expf(v2 - m);
        float e3 = expf(v3 - m);
        float s = (e0 + e1) + (e2 + e3);
#pragma unroll
        for (int off = 16; off > 0; off >>= 1)
            s += __shfl_xor_sync(0xffffffffu, s, off);
        if (lid == 0) sRed[8 + wid] = s;
        __syncthreads();
        s = (sRed[8 + row * 4] + sRed[8 + row * 4 + 1]) +
            (sRed[8 + row * 4 + 2] + sRed[8 + row * 4 + 3]);
        const float inv = 1.f / s;
        *(float4*)&ew[jq] = make_float4(e0 * inv, e1 * inv, e2 * inv, e3 * inv);
        __syncthreads();
    }

    // ---- agg: vectorized __half2 x loads; halves combined via smem ----
    {
        // thread = (jh 0/1, d2 0..127); d = 2*d2
        const int d2 = tid & 127;
        const int jh = tid >> 7;
        const __half2* xb2 = (const __half2*)(g_x_h + (size_t)b * NN * DD);
        const float* p0 = sEw + jh * 256;          // row i0, this j-half
        const float* p1 = sEw + 512 + jh * 256;    // row i1, this j-half
        const int jbase = jh * 256;

        float2 a0 = make_float2(0.f, 0.f);
        float2 a1 = make_float2(0.f, 0.f);
#pragma unroll 4
        for (int j = 0; j < 256; j++) {
            float2 xv = __half22float2(xb2[(size_t)(jbase + j) * 128 + d2]);
            float w0 = p0[j], w1 = p1[j];
            a0.x = fmaf(w0, xv.x, a0.x);
            a0.y = fmaf(w0, xv.y, a0.y);
            a1.x = fmaf(w1, xv.x, a1.x);
            a1.y = fmaf(w1, xv.y, a1.y);
        }
        // scratch in the (now free) A-tile region: [jh][row][256 floats]
        float* sc = (float*)(smem + OFF_A);
        *(float2*)&sc[(jh * 2 + 0) * 256 + d2 * 2] = a0;
        *(float2*)&sc[(jh * 2 + 1) * 256 + d2 * 2] = a1;
        __syncthreads();
        // combine halves: 512 outputs over 256 threads
        float v0 = sc[0 * 256 + tid] + sc[2 * 256 + tid];   // row i0
        float v1 = sc[1 * 256 + tid] + sc[3 * 256 + tid];   // row i1
        g_agg[((size_t)(b * NN + i0)) * DD + tid]     = v0;
        g_agg[((size_t)(b * NN + i0 + 1)) * DD + tid] = v1;
    }
}

// ---------------------------------------------------------------------------
// Kernel C: out = g_agg @ Wg + bg; grid 128, block 512.
// Thread = (h-col, dh); dh splits d-range, 8 rows per thread; smem combine.
// (R14-validated configuration.)
// ---------------------------------------------------------------------------
__global__ __launch_bounds__(512) void out_kernel(
    const float* __restrict__ Wg, const float* __restrict__ bg,
    float* __restrict__ out)
{
    __shared__ float sA[8 * DD];            // 8KB
    __shared__ float sP[2 * 8 * HH];        // 16KB: [dh][row][h]
    const int r0 = blockIdx.x * 8;
    const int tid = threadIdx.x;
    const int h = tid & 255;
    const int dh = tid >> 8;
    const int d0 = dh << 7;
    {
        const float4* src = (const float4*)(g_agg + (size_t)r0 * DD);
        float4* dst = (float4*)sA;
#pragma unroll
        for (int t = tid; t < 8 * DD / 4; t += 512) dst[t] = src[t];
    }
    __syncthreads();

    float acc[8];
    const float bgv = (dh == 0) ? bg[h] : 0.f;
#pragma unroll
    for (int t = 0; t < 8; t++) acc[t] = bgv;

    float wq[2][4];
#pragma unroll
    for (int q = 0; q < 4; q++) wq[0][q] = Wg[(d0 + q) * HH + h];
#pragma unroll 2
    for (int dd = 0; dd < 128; dd += 4) {
        const int cur = (dd >> 2) & 1;
        const int d = d0 + dd;
        if (dd + 4 < 128) {
#pragma unroll
            for (int q = 0; q < 4; q++)
                wq[cur ^ 1][q] = Wg[(d + 4 + q) * HH + h];
        }
#pragma unroll
        for (int t = 0; t < 8; t++) {
            float4 av = *(const float4*)&sA[t * DD + d];
            acc[t] = fmaf(av.x, wq[cur][0],
                     fmaf(av.y, wq[cur][1],
                     fmaf(av.z, wq[cur][2],
                     fmaf(av.w, wq[cur][3], acc[t]))));
        }
    }
#pragma unroll
    for (int t = 0; t < 8; t++)
        sP[dh * 2048 + t * 256 + h] = acc[t];
    __syncthreads();

#pragma unroll
    for (int k = tid; k < 2048; k += 512) {
        float v = sP[k] + sP[k + 2048];
        int row = r0 + (k >> 8);
        out[(size_t)row * HH + (k & 255)] = v;
    }
}

// ---------------------------------------------------------------------------
extern "C" void kernel_launch(void* const* d_in, const int* in_sizes, int n_in,
                              void* d_out, int out_size)
{
    const float* x        = (const float*)d_in[0];
    const float* base_adj = (const float*)d_in[1];
    const float* W1       = (const float*)d_in[2];
    const float* b1       = (const float*)d_in[3];
    const float* W2       = (const float*)d_in[4];
    const float* b2       = (const float*)d_in[5];
    const float* W3       = (const float*)d_in[6];
    const float* b3       = (const float*)d_in[7];
    const float* Wg       = (const float*)d_in[8];
    const float* bg       = (const float*)d_in[9];
    float* out = (float*)d_out;

    cudaFuncSetAttribute(main_kernel,
                         cudaFuncAttributeMaxDynamicSharedMemorySize,
                         SMEM_TOTAL);

    lr_kernel<<<BB * NN / LR_ROWS, 512>>>(x, W1, b1, W2);
    main_kernel<<<dim3(NN / 2, BB), NTHREADS, SMEM_TOTAL>>>(
        base_adj, b2, W3, b3);
    out_kernel<<<BB * NN / 8, 512>>>(Wg, bg, out);
}